// round 12
// baseline (speedup 1.0000x reference)
#include <cuda_runtime.h>
#include <cuda_fp16.h>
#include <cstdint>

#define N_NODES 50000
#define N_EDGES 800000
#define D 96
#define D4 (D / 4)            // 24 float4 (or uint2-of-half) chunks per row

// ---------------- scratch ----------------
__device__ int    g_is64;
__device__ int    g_counts[N_NODES];
__device__ int    g_cursor[N_NODES];
__device__ int    g_row_ptr[N_NODES + 1];
__device__ int    g_bsum[256];
__device__ int2   g_edges[N_EDGES];             // {col, val bits}
__device__ float4 g_Y  [N_NODES * D4];          // fp32 Y = H @ W
__device__ float4 g_T1 [N_NODES * D4];
__device__ float4 g_T2 [N_NODES * D4];
__device__ uint2  g_Yh [N_NODES * D4];          // fp16 shadows (gather operands)
__device__ uint2  g_T1h[N_NODES * D4];
__device__ uint2  g_T2h[N_NODES * D4];

__device__ __forceinline__ int load_idx(const int* __restrict__ p, int i, int is64) {
    return is64 ? p[2 * i] : p[i];   // little-endian low word of int64
}

// ---------------- fused: zero counts + index-dtype probe ----------------
__global__ void zero_detect_kernel(const int* __restrict__ rows) {
    int i = blockIdx.x * blockDim.x + threadIdx.x;
    int stride = gridDim.x * blockDim.x;
    for (; i < N_NODES; i += stride) g_counts[i] = 0;
    if (blockIdx.x == 0) {
        __shared__ int any;
        if (threadIdx.x == 0) any = 0;
        __syncthreads();
        int acc = 0;
        for (int k = 2 * threadIdx.x + 1; k < 20000; k += 2 * blockDim.x)
            acc |= rows[k];
        if (acc) atomicOr(&any, 1);
        __syncthreads();
        if (threadIdx.x == 0) g_is64 = any ? 0 : 1;
    }
}

__global__ void hist_kernel(const int* __restrict__ rows) {
    const int is64 = g_is64;
    int i = blockIdx.x * blockDim.x + threadIdx.x;
    int stride = gridDim.x * blockDim.x;
    for (; i < N_EDGES; i += stride) atomicAdd(&g_counts[load_idx(rows, i, is64)], 1);
}

// --- scan: phase1 (block sums), fused phase2+3 (row_ptr, cursor) ---
#define SCAN_BLOCKS 196          // 196*256 = 50176 >= N_NODES
__global__ void scan_phase1() {
    __shared__ int sm[256];
    int i = blockIdx.x * 256 + threadIdx.x;
    int v = (i < N_NODES) ? g_counts[i] : 0;
    sm[threadIdx.x] = v;
    __syncthreads();
    for (int off = 128; off > 0; off >>= 1) {
        if (threadIdx.x < off) sm[threadIdx.x] += sm[threadIdx.x + off];
        __syncthreads();
    }
    if (threadIdx.x == 0) g_bsum[blockIdx.x] = sm[0];
}

// Each block redundantly scans the 196 block sums (shared barrier loop with
// its own 256-count scan), then writes row_ptr/cursor with its block offset.
__global__ void scan_phase23() {
    __shared__ int sb[256];
    __shared__ int sm[256];
    const int t = threadIdx.x;
    const int i = blockIdx.x * 256 + t;
    sb[t] = (t < SCAN_BLOCKS) ? g_bsum[t] : 0;
    int v = (i < N_NODES) ? g_counts[i] : 0;
    sm[t] = v;
    __syncthreads();
    for (int off = 1; off < 256; off <<= 1) {
        int u1 = (t >= off) ? sb[t - off] : 0;
        int u2 = (t >= off) ? sm[t - off] : 0;
        __syncthreads();
        sb[t] += u1;
        sm[t] += u2;
        __syncthreads();
    }
    if (i < N_NODES) {
        int excl_blk = (blockIdx.x > 0) ? sb[blockIdx.x - 1] : 0;   // inclusive->exclusive
        int p = excl_blk + sm[t] - v;
        g_row_ptr[i] = p;
        g_cursor[i]  = p;
    }
    if (blockIdx.x == 0 && t == 0) g_row_ptr[N_NODES] = N_EDGES;
}

// ---------------- fused scatter + GEMM (independent work, one launch) ----
// blocks [0, GEMM_BLOCKS): Y = H @ W  (fp32 + fp16 shadow)
// blocks [GEMM_BLOCKS, +SCATTER_BLOCKS): CSR scatter of edges
#define GEMM_RPB 16
#define GEMM_BLOCKS (N_NODES / GEMM_RPB)     // 3125
#define SCATTER_BLOCKS 1024
__global__ __launch_bounds__(384) void scatter_gemm_kernel(
        const int* __restrict__ rows, const int* __restrict__ cols,
        const float* __restrict__ vals,
        const float* __restrict__ H, const float* __restrict__ W) {
    if (blockIdx.x < GEMM_BLOCKS) {
        __shared__ float Ws[D * D];
        __shared__ float Hs[GEMM_RPB][D];
        const int tid = threadIdx.x;
        for (int i = tid; i < D * D; i += 384) Ws[i] = W[i];
        const int row0 = blockIdx.x * GEMM_RPB;
        for (int i = tid; i < GEMM_RPB * D; i += 384) {
            int r = i / D, c = i % D;
            Hs[r][c] = H[(row0 + r) * D + c];
        }
        __syncthreads();
        const int j = tid % 96;
        const int rbase = (tid / 96) * 4;
        float acc0 = 0.f, acc1 = 0.f, acc2 = 0.f, acc3 = 0.f;
        #pragma unroll 8
        for (int k = 0; k < D; k++) {
            float w = Ws[k * D + j];
            acc0 = fmaf(Hs[rbase + 0][k], w, acc0);
            acc1 = fmaf(Hs[rbase + 1][k], w, acc1);
            acc2 = fmaf(Hs[rbase + 2][k], w, acc2);
            acc3 = fmaf(Hs[rbase + 3][k], w, acc3);
        }
        float accs[4] = {acc0, acc1, acc2, acc3};
        float*  Yf = (float*)g_Y;              // device-side symbol refs: valid
        __half* Yh = (__half*)g_Yh;
        #pragma unroll
        for (int i = 0; i < 4; i++) {
            int r = row0 + rbase + i;
            Yf[r * D + j] = accs[i];
            Yh[r * D + j] = __float2half_rn(accs[i]);
        }
    } else {
        const int is64 = g_is64;
        int i = (blockIdx.x - GEMM_BLOCKS) * blockDim.x + threadIdx.x;
        int stride = SCATTER_BLOCKS * blockDim.x;
        for (; i < N_EDGES; i += stride) {
            int r = load_idx(rows, i, is64);
            int pos = atomicAdd(&g_cursor[r], 1);
            g_edges[pos] = make_int2(load_idx(cols, i, is64), __float_as_int(vals[i]));
        }
    }
}

// ---------------- SpMM + Chebyshev combine -----------------
// One warp per row; lanes 0..23 own 4 features each.
// Gather uses fp16 shadow Xh (192 B/row); linear terms use fp32 X, P.
// O[r] = a*S(X)[r] + b*X[r] + c*P[r] (+ bias);  Oh = fp16(O) if non-null.
__global__ __launch_bounds__(256) void spmm_kernel(const uint2*  __restrict__ Xh,
                                                   const float4* __restrict__ X,
                                                   const float4* __restrict__ P,
                                                   float4* __restrict__ O,
                                                   uint2*  __restrict__ Oh,
                                                   const float4* __restrict__ bias,
                                                   float a, float b, float c) {
    const int w = (blockIdx.x * blockDim.x + threadIdx.x) >> 5;
    if (w >= N_NODES) return;
    const int lane = threadIdx.x & 31;
    if (lane >= D4) return;
    const int start = g_row_ptr[w];
    const int end   = g_row_ptr[w + 1];

    float ax = 0.f, ay = 0.f, az = 0.f, aw = 0.f;
    #pragma unroll 4
    for (int e = start; e < end; ++e) {
        int2 ed = g_edges[e];                      // warp-uniform broadcast
        float v = __int_as_float(ed.y);
        uint2 h = __ldg(&Xh[ed.x * D4 + lane]);    // 4 halves, 8 B
        float2 f01 = __half22float2(*(const half2*)&h.x);
        float2 f23 = __half22float2(*(const half2*)&h.y);
        ax = fmaf(v, f01.x, ax);
        ay = fmaf(v, f01.y, ay);
        az = fmaf(v, f23.x, az);
        aw = fmaf(v, f23.y, aw);
    }

    const int base = w * D4 + lane;
    float4 xs = X[base];
    float4 t;
    t.x = a * ax + b * xs.x;
    t.y = a * ay + b * xs.y;
    t.z = a * az + b * xs.z;
    t.w = a * aw + b * xs.w;
    if (P) {
        float4 p = P[base];
        t.x += c * p.x; t.y += c * p.y; t.z += c * p.z; t.w += c * p.w;
    }
    if (bias) {
        float4 bv = bias[lane];
        t.x += bv.x; t.y += bv.y; t.z += bv.z; t.w += bv.w;
    }
    O[base] = t;
    if (Oh) {
        uint2 hh;
        *(half2*)&hh.x = __floats2half2_rn(t.x, t.y);
        *(half2*)&hh.y = __floats2half2_rn(t.z, t.w);
        Oh[base] = hh;
    }
}

// ---------------- launch ----------------
extern "C" void kernel_launch(void* const* d_in, const int* in_sizes, int n_in,
                              void* d_out, int out_size) {
    const int*   rows = (const int*)  d_in[0];
    const int*   cols = (const int*)  d_in[1];
    const float* vals = (const float*)d_in[2];
    const float* H    = (const float*)d_in[3];
    const float* W    = (const float*)d_in[4];
    const float* bias = (const float*)d_in[5];
    float* out = (float*)d_out;

    // Real DEVICE addresses (host-side symbol names are shadow addresses).
    float4 *Yp = nullptr, *T1p = nullptr, *T2p = nullptr;
    uint2  *Yhp = nullptr, *T1hp = nullptr, *T2hp = nullptr;
    cudaGetSymbolAddress((void**)&Yp,   g_Y);
    cudaGetSymbolAddress((void**)&T1p,  g_T1);
    cudaGetSymbolAddress((void**)&T2p,  g_T2);
    cudaGetSymbolAddress((void**)&Yhp,  g_Yh);
    cudaGetSymbolAddress((void**)&T1hp, g_T1h);
    cudaGetSymbolAddress((void**)&T2hp, g_T2h);

    // CSR build + GEMM (every call — no caching)
    zero_detect_kernel<<<256, 256>>>(rows);
    hist_kernel<<<1024, 256>>>(rows);
    scan_phase1<<<SCAN_BLOCKS, 256>>>();
    scan_phase23<<<SCAN_BLOCKS, 256>>>();
    scatter_gemm_kernel<<<GEMM_BLOCKS + SCATTER_BLOCKS, 384>>>(rows, cols, vals, H, W);

    const int SPMM_BLOCKS = (N_NODES * 32 + 255) / 256;
    float4* out4 = (float4*)out;
    const float4* bias4 = (const float4*)bias;
    // T1 = 2*S(Y) - Y
    spmm_kernel<<<SPMM_BLOCKS, 256>>>(Yhp,  Yp,  nullptr, T1p, T1hp, nullptr, 2.f, -1.f, 0.f);
    // T2 = 4*S(T1) - 2*T1 - Y
    spmm_kernel<<<SPMM_BLOCKS, 256>>>(T1hp, T1p, Yp,      T2p, T2hp, nullptr, 4.f, -2.f, -1.f);
    // out = Y + T1 + T2 + T3 + bias == 4*S(T2) - T2 + Y + bias  (T1 cancels)
    spmm_kernel<<<SPMM_BLOCKS, 256>>>(T2hp, T2p, Yp,      out4, nullptr, bias4, 4.f, -1.f, 1.f);
}

// round 13
// speedup vs baseline: 1.0113x; 1.0113x over previous
#include <cuda_runtime.h>
#include <cuda_fp16.h>
#include <cstdint>

#define N_NODES 50000
#define N_EDGES 800000
#define D 96
#define D4 (D / 4)            // 24 float4 (or uint2-of-half) chunks per row

// ---------------- scratch ----------------
__device__ int    g_is64;
__device__ int    g_counts[N_NODES];
__device__ int    g_cursor[N_NODES];
__device__ int    g_row_ptr[N_NODES + 1];
__device__ int    g_bsum[256];
__device__ int2   g_edges[N_EDGES];             // {col, val bits}
__device__ float4 g_Y  [N_NODES * D4];          // fp32 Y = H @ W
__device__ float4 g_T1 [N_NODES * D4];
__device__ float4 g_T2 [N_NODES * D4];
__device__ uint2  g_Yh [N_NODES * D4];          // fp16 shadows (gather operands)
__device__ uint2  g_T1h[N_NODES * D4];
__device__ uint2  g_T2h[N_NODES * D4];

__device__ __forceinline__ int load_idx(const int* __restrict__ p, int i, int is64) {
    return is64 ? p[2 * i] : p[i];   // little-endian low word of int64
}

// ---------------- fused: zero counts + index-dtype probe ----------------
__global__ void zero_detect_kernel(const int* __restrict__ rows) {
    int i = blockIdx.x * blockDim.x + threadIdx.x;
    int stride = gridDim.x * blockDim.x;
    for (; i < N_NODES; i += stride) g_counts[i] = 0;
    if (blockIdx.x == 0) {
        __shared__ int any;
        if (threadIdx.x == 0) any = 0;
        __syncthreads();
        int acc = 0;
        for (int k = 2 * threadIdx.x + 1; k < 20000; k += 2 * blockDim.x)
            acc |= rows[k];
        if (acc) atomicOr(&any, 1);
        __syncthreads();
        if (threadIdx.x == 0) g_is64 = any ? 0 : 1;
    }
}

__global__ void hist_kernel(const int* __restrict__ rows) {
    const int is64 = g_is64;
    int i = blockIdx.x * blockDim.x + threadIdx.x;
    int stride = gridDim.x * blockDim.x;
    for (; i < N_EDGES; i += stride) atomicAdd(&g_counts[load_idx(rows, i, is64)], 1);
}

// --- scan: phase1 (block sums), fused phase2+3 (row_ptr, cursor) ---
#define SCAN_BLOCKS 196          // 196*256 = 50176 >= N_NODES
__global__ void scan_phase1() {
    __shared__ int sm[256];
    int i = blockIdx.x * 256 + threadIdx.x;
    int v = (i < N_NODES) ? g_counts[i] : 0;
    sm[threadIdx.x] = v;
    __syncthreads();
    for (int off = 128; off > 0; off >>= 1) {
        if (threadIdx.x < off) sm[threadIdx.x] += sm[threadIdx.x + off];
        __syncthreads();
    }
    if (threadIdx.x == 0) g_bsum[blockIdx.x] = sm[0];
}

// Each block redundantly scans the 196 block sums (shared barrier loop with
// its own 256-count scan), then writes row_ptr/cursor with its block offset.
__global__ void scan_phase23() {
    __shared__ int sb[256];
    __shared__ int sm[256];
    const int t = threadIdx.x;
    const int i = blockIdx.x * 256 + t;
    sb[t] = (t < SCAN_BLOCKS) ? g_bsum[t] : 0;
    int v = (i < N_NODES) ? g_counts[i] : 0;
    sm[t] = v;
    __syncthreads();
    for (int off = 1; off < 256; off <<= 1) {
        int u1 = (t >= off) ? sb[t - off] : 0;
        int u2 = (t >= off) ? sm[t - off] : 0;
        __syncthreads();
        sb[t] += u1;
        sm[t] += u2;
        __syncthreads();
    }
    if (i < N_NODES) {
        int excl_blk = (blockIdx.x > 0) ? sb[blockIdx.x - 1] : 0;   // inclusive->exclusive
        int p = excl_blk + sm[t] - v;
        g_row_ptr[i] = p;
        g_cursor[i]  = p;
    }
    if (blockIdx.x == 0 && t == 0) g_row_ptr[N_NODES] = N_EDGES;
}

// ---------------- fused scatter + GEMM (independent work, one launch) ----
// blocks [0, GEMM_BLOCKS): Y = H @ W  (fp32 + fp16 shadow)
// blocks [GEMM_BLOCKS, +SCATTER_BLOCKS): CSR scatter of edges
#define GEMM_RPB 16
#define GEMM_BLOCKS (N_NODES / GEMM_RPB)     // 3125
#define SCATTER_BLOCKS 1024
__global__ __launch_bounds__(384) void scatter_gemm_kernel(
        const int* __restrict__ rows, const int* __restrict__ cols,
        const float* __restrict__ vals,
        const float* __restrict__ H, const float* __restrict__ W) {
    if (blockIdx.x < GEMM_BLOCKS) {
        __shared__ float Ws[D * D];
        __shared__ float Hs[GEMM_RPB][D];
        const int tid = threadIdx.x;
        for (int i = tid; i < D * D; i += 384) Ws[i] = W[i];
        const int row0 = blockIdx.x * GEMM_RPB;
        for (int i = tid; i < GEMM_RPB * D; i += 384) {
            int r = i / D, c = i % D;
            Hs[r][c] = H[(row0 + r) * D + c];
        }
        __syncthreads();
        const int j = tid % 96;
        const int rbase = (tid / 96) * 4;
        float acc0 = 0.f, acc1 = 0.f, acc2 = 0.f, acc3 = 0.f;
        #pragma unroll 8
        for (int k = 0; k < D; k++) {
            float w = Ws[k * D + j];
            acc0 = fmaf(Hs[rbase + 0][k], w, acc0);
            acc1 = fmaf(Hs[rbase + 1][k], w, acc1);
            acc2 = fmaf(Hs[rbase + 2][k], w, acc2);
            acc3 = fmaf(Hs[rbase + 3][k], w, acc3);
        }
        float accs[4] = {acc0, acc1, acc2, acc3};
        float*  Yf = (float*)g_Y;              // device-side symbol refs: valid
        __half* Yh = (__half*)g_Yh;
        #pragma unroll
        for (int i = 0; i < 4; i++) {
            int r = row0 + rbase + i;
            Yf[r * D + j] = accs[i];
            Yh[r * D + j] = __float2half_rn(accs[i]);
        }
    } else {
        const int is64 = g_is64;
        int i = (blockIdx.x - GEMM_BLOCKS) * blockDim.x + threadIdx.x;
        int stride = SCATTER_BLOCKS * blockDim.x;
        for (; i < N_EDGES; i += stride) {
            int r = load_idx(rows, i, is64);
            int pos = atomicAdd(&g_cursor[r], 1);
            g_edges[pos] = make_int2(load_idx(cols, i, is64), __float_as_int(vals[i]));
        }
    }
}

// ---------------- SpMM + Chebyshev combine -----------------
// One warp per row; lanes 0..23 own 4 features each.
// Gather uses fp16 shadow Xh (192 B/row); linear terms use fp32 X, P.
// O[r] = a*S(X)[r] + b*X[r] + c*P[r] (+ bias);  Oh = fp16(O) if non-null.
__global__ __launch_bounds__(256) void spmm_kernel(const uint2*  __restrict__ Xh,
                                                   const float4* __restrict__ X,
                                                   const float4* __restrict__ P,
                                                   float4* __restrict__ O,
                                                   uint2*  __restrict__ Oh,
                                                   const float4* __restrict__ bias,
                                                   float a, float b, float c) {
    const int w = (blockIdx.x * blockDim.x + threadIdx.x) >> 5;
    if (w >= N_NODES) return;
    const int lane = threadIdx.x & 31;
    if (lane >= D4) return;
    const int start = g_row_ptr[w];
    const int end   = g_row_ptr[w + 1];

    float ax = 0.f, ay = 0.f, az = 0.f, aw = 0.f;
    #pragma unroll 4
    for (int e = start; e < end; ++e) {
        int2 ed = g_edges[e];                      // warp-uniform broadcast
        float v = __int_as_float(ed.y);
        uint2 h = __ldg(&Xh[ed.x * D4 + lane]);    // 4 halves, 8 B
        float2 f01 = __half22float2(*(const half2*)&h.x);
        float2 f23 = __half22float2(*(const half2*)&h.y);
        ax = fmaf(v, f01.x, ax);
        ay = fmaf(v, f01.y, ay);
        az = fmaf(v, f23.x, az);
        aw = fmaf(v, f23.y, aw);
    }

    const int base = w * D4 + lane;
    float4 xs = X[base];
    float4 t;
    t.x = a * ax + b * xs.x;
    t.y = a * ay + b * xs.y;
    t.z = a * az + b * xs.z;
    t.w = a * aw + b * xs.w;
    if (P) {
        float4 p = P[base];
        t.x += c * p.x; t.y += c * p.y; t.z += c * p.z; t.w += c * p.w;
    }
    if (bias) {
        float4 bv = bias[lane];
        t.x += bv.x; t.y += bv.y; t.z += bv.z; t.w += bv.w;
    }
    O[base] = t;
    if (Oh) {
        uint2 hh;
        *(half2*)&hh.x = __floats2half2_rn(t.x, t.y);
        *(half2*)&hh.y = __floats2half2_rn(t.z, t.w);
        Oh[base] = hh;
    }
}

// ---------------- launch ----------------
extern "C" void kernel_launch(void* const* d_in, const int* in_sizes, int n_in,
                              void* d_out, int out_size) {
    const int*   rows = (const int*)  d_in[0];
    const int*   cols = (const int*)  d_in[1];
    const float* vals = (const float*)d_in[2];
    const float* H    = (const float*)d_in[3];
    const float* W    = (const float*)d_in[4];
    const float* bias = (const float*)d_in[5];
    float* out = (float*)d_out;

    // Real DEVICE addresses (host-side symbol names are shadow addresses).
    float4 *Yp = nullptr, *T1p = nullptr, *T2p = nullptr;
    uint2  *Yhp = nullptr, *T1hp = nullptr, *T2hp = nullptr;
    cudaGetSymbolAddress((void**)&Yp,   g_Y);
    cudaGetSymbolAddress((void**)&T1p,  g_T1);
    cudaGetSymbolAddress((void**)&T2p,  g_T2);
    cudaGetSymbolAddress((void**)&Yhp,  g_Yh);
    cudaGetSymbolAddress((void**)&T1hp, g_T1h);
    cudaGetSymbolAddress((void**)&T2hp, g_T2h);

    // CSR build + GEMM (every call — no caching)
    zero_detect_kernel<<<256, 256>>>(rows);
    hist_kernel<<<1024, 256>>>(rows);
    scan_phase1<<<SCAN_BLOCKS, 256>>>();
    scan_phase23<<<SCAN_BLOCKS, 256>>>();
    scatter_gemm_kernel<<<GEMM_BLOCKS + SCATTER_BLOCKS, 384>>>(rows, cols, vals, H, W);

    const int SPMM_BLOCKS = (N_NODES * 32 + 255) / 256;
    float4* out4 = (float4*)out;
    const float4* bias4 = (const float4*)bias;
    // T1 = 2*S(Y) - Y
    spmm_kernel<<<SPMM_BLOCKS, 256>>>(Yhp,  Yp,  nullptr, T1p, T1hp, nullptr, 2.f, -1.f, 0.f);
    // T2 = 4*S(T1) - 2*T1 - Y
    spmm_kernel<<<SPMM_BLOCKS, 256>>>(T1hp, T1p, Yp,      T2p, T2hp, nullptr, 4.f, -2.f, -1.f);
    // out = Y + T1 + T2 + T3 + bias == 4*S(T2) - T2 + Y + bias  (T1 cancels)
    spmm_kernel<<<SPMM_BLOCKS, 256>>>(T2hp, T2p, Yp,      out4, nullptr, bias4, 4.f, -1.f, 1.f);
}